// round 14
// baseline (speedup 1.0000x reference)
#include <cuda_runtime.h>
#include <stdint.h>

// Problem constants: B=16, L=4096, H=768 (fp32)
#define B_ 16
#define L_ 4096
#define H_ 768
#define H4 (H_ / 4)            // 192 float4 lanes per row
#define TOK_PER_BLK 16         // tokens per tile
#define SROWS 4                // rows per pipeline stage (12 KB)
#define NSTAGES 3              // pipeline depth (36 KB smem)
#define NCWARPS 6              // consumer warps (192 lanes)
#define NTHREADS 224           // 6 consumer warps + 1 producer warp
#define TILES_PER_BATCH (L_ / TOK_PER_BLK)   // 256
#define NUM_TILES (B_ * TILES_PER_BATCH)     // 4096
#define GRID_BLOCKS (148 * 6)                // 888: one residency wave
#define MAX_TILES_PER_CTA ((NUM_TILES + GRID_BLOCKS - 1) / GRID_BLOCKS)  // 5

__device__ __forceinline__ uint32_t smem_u32(const void* p) {
    uint32_t a;
    asm("{ .reg .u64 tmp; cvta.to.shared.u64 tmp, %1; cvt.u32.u64 %0, tmp; }"
        : "=r"(a) : "l"(p));
    return a;
}
__device__ __forceinline__ void mbar_init(uint32_t mbar, uint32_t cnt) {
    asm volatile("mbarrier.init.shared.b64 [%0], %1;" :: "r"(mbar), "r"(cnt) : "memory");
}
__device__ __forceinline__ void mbar_expect_tx(uint32_t mbar, uint32_t bytes) {
    asm volatile("mbarrier.arrive.expect_tx.shared.b64 _, [%0], %1;"
                 :: "r"(mbar), "r"(bytes) : "memory");
}
__device__ __forceinline__ void mbar_arrive(uint32_t mbar) {
    asm volatile("mbarrier.arrive.shared.b64 _, [%0];" :: "r"(mbar) : "memory");
}
__device__ __forceinline__ void mbar_wait(uint32_t mbar, uint32_t parity) {
    uint32_t done;
    asm volatile(
        "{\n\t.reg .pred p;\n\t"
        "mbarrier.try_wait.parity.acquire.cta.shared::cta.b64 p, [%1], %2;\n\t"
        "selp.b32 %0, 1, 0, p;\n\t}"
        : "=r"(done) : "r"(mbar), "r"(parity) : "memory");
    if (!done) {
        asm volatile(
            "{\n\t.reg .pred P1;\n\t"
            "WL_%=:\n\t"
            "mbarrier.try_wait.parity.acquire.cta.shared::cta.b64 P1, [%0], %1, 0x989680;\n\t"
            "@P1 bra.uni WD_%=;\n\t"
            "bra.uni WL_%=;\n\t"
            "WD_%=:\n\t}"
            :: "r"(mbar), "r"(parity) : "memory");
    }
}
__device__ __forceinline__ void bulk_copy_g2s(uint32_t dst_smem, const void* src,
                                              uint32_t bytes, uint32_t mbar) {
    asm volatile(
        "cp.async.bulk.shared::cta.global.mbarrier::complete_tx::bytes "
        "[%0], [%1], %2, [%3];"
        :: "r"(dst_smem), "l"(src), "r"(bytes), "r"(mbar) : "memory");
}

__global__ __launch_bounds__(NTHREADS)
void token_segment_sum_kernel(const float* __restrict__ x,
                              const int*   __restrict__ seg,
                              float*       __restrict__ out)
{
    __shared__ alignas(16) float4 buf[NSTAGES][SROWS * H4];   // 36 KB
    __shared__ alignas(8) uint64_t mb_full[NSTAGES];
    __shared__ alignas(8) uint64_t mb_empty[NSTAGES];
    __shared__ int bndt[MAX_TILES_PER_CTA][TOK_PER_BLK + 1];  // all my tiles' bounds

    const int bid = blockIdx.x;
    const int t   = threadIdx.x;        // 0..223
    const int wid = t >> 5;             // 0..6 (warp 6 = producer)
    const int lane = t & 31;

    // number of tiles this block owns (strided assignment: bid + k*GRID)
    const int nt = (NUM_TILES - bid + GRID_BLOCKS - 1) / GRID_BLOCKS;

    if (t < NSTAGES) {
        mbar_init(smem_u32(&mb_full[t]), 1);         // completed by TMA tx bytes
        mbar_init(smem_u32(&mb_empty[t]), NCWARPS);  // one arrive per consumer warp
    }

    // compute ALL tile bounds in-kernel: one binary search per thread
    // (nt*(17) <= 85 searches across 224 threads, done once per block)
    for (int idx = t; idx < nt * (TOK_PER_BLK + 1); idx += NTHREADS) {
        const int k = idx / (TOK_PER_BLK + 1);
        const int i = idx % (TOK_PER_BLK + 1);
        const int tileIdx = bid + k * GRID_BLOCKS;
        const int b  = tileIdx / TILES_PER_BATCH;
        const int j0 = (tileIdx % TILES_PER_BATCH) * TOK_PER_BLK;
        const int* __restrict__ segb = seg + b * L_;
        // lower_bound: first p with segb[p] >= (j0 + i)
        const int target = j0 + i;
        int lo = 0, hi = L_;
        #pragma unroll 1
        while (lo < hi) {
            int mid = (lo + hi) >> 1;
            if (__ldg(&segb[mid]) < target) lo = mid + 1; else hi = mid;
        }
        bndt[k][i] = lo;
    }
    __syncthreads();

    if (wid == NCWARPS) {
        // -------- PRODUCER WARP: stream chunks continuously across tiles ----
        if (lane == 0) {
            int cc = 0;   // global chunk counter (stage = cc%3, lap = cc/3)
            #pragma unroll 1
            for (int k = 0; k < nt; k++) {
                const int tileIdx = bid + k * GRID_BLOCKS;
                const int b = tileIdx / TILES_PER_BATCH;
                const float4* __restrict__ xb =
                    reinterpret_cast<const float4*>(x + (size_t)b * L_ * H_);
                const int s0 = bndt[k][0];
                const int s1 = bndt[k][TOK_PER_BLK];
                #pragma unroll 1
                for (int rbase = s0; rbase < s1; rbase += SROWS) {
                    const int s = cc % NSTAGES;
                    const int u = cc / NSTAGES;
                    if (u > 0)
                        mbar_wait(smem_u32(&mb_empty[s]), (uint32_t)((u - 1) & 1));
                    const uint32_t bytes =
                        (uint32_t)min(SROWS, s1 - rbase) * (H_ * 4);
                    const uint32_t fm = smem_u32(&mb_full[s]);
                    mbar_expect_tx(fm, bytes);
                    bulk_copy_g2s(smem_u32(&buf[s][0]),
                                  &xb[(size_t)rbase * H4], bytes, fm);
                    cc++;
                }
            }
        }
        return;
    }

    // -------- CONSUMER WARPS (192 lanes) --------------------------------
    int cc = 0;   // must mirror producer's chunk sequence exactly
    #pragma unroll 1
    for (int k = 0; k < nt; k++) {
        const int tileIdx = bid + k * GRID_BLOCKS;
        const int b  = tileIdx / TILES_PER_BATCH;
        const int j0 = (tileIdx % TILES_PER_BATCH) * TOK_PER_BLK;
        float4* __restrict__ ob =
            reinterpret_cast<float4*>(out + (size_t)b * L_ * H_);

        const int s0 = bndt[k][0];
        const int s1 = bndt[k][TOK_PER_BLK];

        int j = 0;
        // tokens empty at the very start (bnd[j+1] == s0) -> zero rows
        #pragma unroll 1
        while (j < TOK_PER_BLK && bndt[k][j + 1] == s0) {
            ob[(size_t)(j0 + j) * H4 + t] = make_float4(0.f, 0.f, 0.f, 0.f);
            j++;
        }

        int nb = (j < TOK_PER_BLK) ? bndt[k][j + 1] : -1;
        float4 acc = make_float4(0.f, 0.f, 0.f, 0.f);

        #pragma unroll 1
        for (int rbase = s0; rbase < s1; rbase += SROWS) {
            const int s = cc % NSTAGES;
            const uint32_t ph = (uint32_t)((cc / NSTAGES) & 1);
            const int n = min(SROWS, s1 - rbase);

            mbar_wait(smem_u32(&mb_full[s]), ph);

            #pragma unroll
            for (int i = 0; i < SROWS; i++) {
                if (i < n) {
                    float4 v = buf[s][i * H4 + t];
                    acc.x += v.x; acc.y += v.y;
                    acc.z += v.z; acc.w += v.w;
                    const int pos1 = rbase + i + 1;
                    if (pos1 == nb) {          // token(s) end here
                        do {
                            ob[(size_t)(j0 + j) * H4 + t] = acc;
                            acc = make_float4(0.f, 0.f, 0.f, 0.f);
                            j++;
                            nb = (j < TOK_PER_BLK) ? bndt[k][j + 1] : -1;
                        } while (nb == pos1);  // equal bounds = empty tokens
                    }
                }
            }

            // release the stage — ONE arrive per consumer warp
            __syncwarp();
            if (lane == 0) mbar_arrive(smem_u32(&mb_empty[s]));
            cc++;
        }
    }
}

extern "C" void kernel_launch(void* const* d_in, const int* in_sizes, int n_in,
                              void* d_out, int out_size)
{
    const float* x   = (const float*)d_in[0];   // sequence_output  [B, L, H] f32
    const int*   seg = (const int*)  d_in[1];   // wordpiece_to_token [B, L] i32
    float*       out = (float*)d_out;           // [B, L, H] f32

    dim3 grid(GRID_BLOCKS);                     // 888 persistent blocks
    dim3 block(NTHREADS);                       // 224 threads (6+1 warps)
    token_segment_sum_kernel<<<grid, block>>>(x, seg, out);
}

// round 15
// speedup vs baseline: 1.0146x; 1.0146x over previous
#include <cuda_runtime.h>
#include <stdint.h>

// Problem constants: B=16, L=4096, H=768 (fp32)
#define B_ 16
#define L_ 4096
#define H_ 768
#define H4 (H_ / 4)            // 192 float4 lanes per row
#define SROWS 4                // rows per pipeline stage (12 KB)
#define NSTAGES 3              // pipeline depth (36 KB smem)
#define NCWARPS 6              // consumer warps (192 lanes)
#define NTHREADS 224           // 6 consumer warps + 1 producer warp
#define NUM_TOK_TOT (B_ * L_)                  // 65536
#define GRID_BLOCKS (148 * 6)                  // 888: one residency wave
#define MAX_BND 84                             // >= max tokens/block + 2
#define WMARGIN 256                            // search window margin (~8 sigma)

__device__ __forceinline__ uint32_t smem_u32(const void* p) {
    uint32_t a;
    asm("{ .reg .u64 tmp; cvta.to.shared.u64 tmp, %1; cvt.u32.u64 %0, tmp; }"
        : "=r"(a) : "l"(p));
    return a;
}
__device__ __forceinline__ void mbar_init(uint32_t mbar, uint32_t cnt) {
    asm volatile("mbarrier.init.shared.b64 [%0], %1;" :: "r"(mbar), "r"(cnt) : "memory");
}
__device__ __forceinline__ void mbar_expect_tx(uint32_t mbar, uint32_t bytes) {
    asm volatile("mbarrier.arrive.expect_tx.shared.b64 _, [%0], %1;"
                 :: "r"(mbar), "r"(bytes) : "memory");
}
__device__ __forceinline__ void mbar_arrive(uint32_t mbar) {
    asm volatile("mbarrier.arrive.shared.b64 _, [%0];" :: "r"(mbar) : "memory");
}
__device__ __forceinline__ void mbar_wait(uint32_t mbar, uint32_t parity) {
    uint32_t done;
    asm volatile(
        "{\n\t.reg .pred p;\n\t"
        "mbarrier.try_wait.parity.acquire.cta.shared::cta.b64 p, [%1], %2;\n\t"
        "selp.b32 %0, 1, 0, p;\n\t}"
        : "=r"(done) : "r"(mbar), "r"(parity) : "memory");
    if (!done) {
        asm volatile(
            "{\n\t.reg .pred P1;\n\t"
            "WL_%=:\n\t"
            "mbarrier.try_wait.parity.acquire.cta.shared::cta.b64 P1, [%0], %1, 0x989680;\n\t"
            "@P1 bra.uni WD_%=;\n\t"
            "bra.uni WL_%=;\n\t"
            "WD_%=:\n\t}"
            :: "r"(mbar), "r"(parity) : "memory");
    }
}
__device__ __forceinline__ void bulk_copy_g2s(uint32_t dst_smem, const void* src,
                                              uint32_t bytes, uint32_t mbar) {
    asm volatile(
        "cp.async.bulk.shared::cta.global.mbarrier::complete_tx::bytes "
        "[%0], [%1], %2, [%3];"
        :: "r"(dst_smem), "l"(src), "r"(bytes), "r"(mbar) : "memory");
}

__global__ __launch_bounds__(NTHREADS)
void token_segment_sum_kernel(const float* __restrict__ x,
                              const int*   __restrict__ seg,
                              float*       __restrict__ out)
{
    __shared__ alignas(16) float4 buf[NSTAGES][SROWS * H4];   // 36 KB
    __shared__ alignas(8) uint64_t mb_full[NSTAGES];
    __shared__ alignas(8) uint64_t mb_empty[NSTAGES];
    __shared__ int sbnd[MAX_BND];     // bounds for all my tokens (flat, per segment)

    const int bid  = blockIdx.x;
    const int t    = threadIdx.x;     // 0..223
    const int wid  = t >> 5;          // 0..6 (warp 6 = producer)
    const int lane = t & 31;

    // contiguous global token range [g0, g1)
    const int g0 = (int)(((int64_t)bid       * NUM_TOK_TOT) / GRID_BLOCKS);
    const int g1 = (int)(((int64_t)(bid + 1) * NUM_TOK_TOT) / GRID_BLOCKS);

    // split into 1 or 2 per-batch segments
    const int b0   = g0 / L_;
    const int e0   = min(g1, (b0 + 1) * L_);
    const int nseg = (g1 > e0) ? 2 : 1;
    int  sb[2], sjlo[2], sjcnt[2], soff[2];
    sb[0] = b0;     sjlo[0] = g0 - b0 * L_; sjcnt[0] = e0 - g0; soff[0] = 0;
    sb[1] = b0 + 1; sjlo[1] = 0;            sjcnt[1] = g1 - e0; soff[1] = sjcnt[0] + 1;

    if (t < NSTAGES) {
        mbar_init(smem_u32(&mb_full[t]), 1);         // completed by TMA tx bytes
        mbar_init(smem_u32(&mb_empty[t]), NCWARPS);  // one arrive per consumer warp
    }

    // ---- bounds via smem-staged windowed search (buf reused as staging) ----
    int* wbuf = reinterpret_cast<int*>(&buf[0][0]);
    #pragma unroll 1
    for (int sgi = 0; sgi < nseg; sgi++) {
        const int b    = sb[sgi];
        const int jlo  = sjlo[sgi];
        const int jcnt = sjcnt[sgi];
        const int jhi  = jlo + jcnt - 1;
        const int* __restrict__ segb = seg + b * L_;

        const int w_lo = max(0, jlo - WMARGIN);
        const int w_hi = min(L_, jhi + 1 + WMARGIN);
        const int wlen = w_hi - w_lo;

        __syncthreads();   // wbuf free (init / previous segment done)
        for (int i = t; i < wlen; i += NTHREADS)
            wbuf[i] = __ldg(&segb[w_lo + i]);
        __syncthreads();

        // window must bracket all lower bounds for targets jlo..jhi+1
        const bool valid =
            (w_lo == 0  || __ldg(&segb[w_lo - 1]) < jlo) &&
            (w_hi == L_ || __ldg(&segb[w_hi]) >= jhi + 1);

        if (t <= jcnt) {
            const int target = jlo + t;
            int lo, hi;
            if (valid) {               // search smem window
                lo = 0; hi = wlen;
                #pragma unroll 1
                while (lo < hi) {
                    int mid = (lo + hi) >> 1;
                    if (wbuf[mid] < target) lo = mid + 1; else hi = mid;
                }
                lo += w_lo;
            } else {                   // fallback: global search (any input)
                lo = 0; hi = L_;
                #pragma unroll 1
                while (lo < hi) {
                    int mid = (lo + hi) >> 1;
                    if (__ldg(&segb[mid]) < target) lo = mid + 1; else hi = mid;
                }
            }
            sbnd[soff[sgi] + t] = lo;
        }
    }
    __syncthreads();   // bounds ready; buf free for the pipeline

    if (wid == NCWARPS) {
        // -------- PRODUCER WARP: continuous chunk stream across segments ----
        if (lane == 0) {
            int cc = 0;   // global chunk counter (stage = cc%3, lap = cc/3)
            #pragma unroll 1
            for (int sgi = 0; sgi < nseg; sgi++) {
                const float4* __restrict__ xb = reinterpret_cast<const float4*>(
                    x + (size_t)sb[sgi] * L_ * H_);
                const int S0 = sbnd[soff[sgi]];
                const int S1 = sbnd[soff[sgi] + sjcnt[sgi]];
                #pragma unroll 1
                for (int rbase = S0; rbase < S1; rbase += SROWS) {
                    const int s = cc % NSTAGES;
                    const int u = cc / NSTAGES;
                    if (u > 0)
                        mbar_wait(smem_u32(&mb_empty[s]), (uint32_t)((u - 1) & 1));
                    const uint32_t bytes =
                        (uint32_t)min(SROWS, S1 - rbase) * (H_ * 4);
                    const uint32_t fm = smem_u32(&mb_full[s]);
                    mbar_expect_tx(fm, bytes);
                    bulk_copy_g2s(smem_u32(&buf[s][0]),
                                  &xb[(size_t)rbase * H4], bytes, fm);
                    cc++;
                }
            }
        }
        return;
    }

    // -------- CONSUMER WARPS (192 lanes) ---------------------------------
    int cc = 0;   // mirrors producer's chunk sequence exactly
    #pragma unroll 1
    for (int sgi = 0; sgi < nseg; sgi++) {
        const int b    = sb[sgi];
        const int jlo  = sjlo[sgi];
        const int jcnt = sjcnt[sgi];
        const int off  = soff[sgi];
        float4* __restrict__ ob =
            reinterpret_cast<float4*>(out + (size_t)b * L_ * H_);

        const int S0 = sbnd[off];
        const int S1 = sbnd[off + jcnt];

        int j = 0;
        // tokens empty at the very start (bnd == S0) -> zero rows
        #pragma unroll 1
        while (j < jcnt && sbnd[off + j + 1] == S0) {
            ob[(size_t)(jlo + j) * H4 + t] = make_float4(0.f, 0.f, 0.f, 0.f);
            j++;
        }

        int nb = (j < jcnt) ? sbnd[off + j + 1] : -1;
        float4 acc = make_float4(0.f, 0.f, 0.f, 0.f);

        #pragma unroll 1
        for (int rbase = S0; rbase < S1; rbase += SROWS) {
            const int s = cc % NSTAGES;
            const uint32_t ph = (uint32_t)((cc / NSTAGES) & 1);
            const int n = min(SROWS, S1 - rbase);

            mbar_wait(smem_u32(&mb_full[s]), ph);

            #pragma unroll
            for (int i = 0; i < SROWS; i++) {
                if (i < n) {
                    float4 v = buf[s][i * H4 + t];
                    acc.x += v.x; acc.y += v.y;
                    acc.z += v.z; acc.w += v.w;
                    const int pos1 = rbase + i + 1;
                    if (pos1 == nb) {          // token(s) end here
                        do {
                            ob[(size_t)(jlo + j) * H4 + t] = acc;
                            acc = make_float4(0.f, 0.f, 0.f, 0.f);
                            j++;
                            nb = (j < jcnt) ? sbnd[off + j + 1] : -1;
                        } while (nb == pos1);  // equal bounds = empty tokens
                    }
                }
            }

            // release the stage — ONE arrive per consumer warp
            __syncwarp();
            if (lane == 0) mbar_arrive(smem_u32(&mb_empty[s]));
            cc++;
        }
    }
}

extern "C" void kernel_launch(void* const* d_in, const int* in_sizes, int n_in,
                              void* d_out, int out_size)
{
    const float* x   = (const float*)d_in[0];   // sequence_output  [B, L, H] f32
    const int*   seg = (const int*)  d_in[1];   // wordpiece_to_token [B, L] i32
    float*       out = (float*)d_out;           // [B, L, H] f32

    dim3 grid(GRID_BLOCKS);                     // 888 persistent blocks
    dim3 block(NTHREADS);                       // 224 threads (6+1 warps)
    token_segment_sum_kernel<<<grid, block>>>(x, seg, out);
}

// round 16
// speedup vs baseline: 1.0234x; 1.0087x over previous
#include <cuda_runtime.h>
#include <stdint.h>

// Problem constants: B=16, L=4096, H=768 (fp32)
#define B_ 16
#define L_ 4096
#define H_ 768
#define H4 (H_ / 4)            // 192 float4 lanes per row
#define TOK_PER_BLK 16         // tokens per tile
#define SROWS 4                // rows per pipeline stage (12 KB)
#define NSTAGES 3              // pipeline depth (36 KB smem)
#define NCWARPS 6              // consumer warps (192 lanes)
#define NTHREADS 224           // 6 consumer warps + 1 producer warp
#define TILES_PER_BATCH (L_ / TOK_PER_BLK)   // 256
#define NUM_TILES (B_ * TILES_PER_BATCH)     // 4096
#define GRID_BLOCKS (148 * 6)                // 888: one residency wave
#define MAX_TILES_PER_CTA ((NUM_TILES + GRID_BLOCKS - 1) / GRID_BLOCKS)  // 5
#define WMARGIN 256                          // window margin (~8 sigma)
#define WLEN 544                             // >= TOK_PER_BLK+1 + 2*WMARGIN

__device__ __forceinline__ uint32_t smem_u32(const void* p) {
    uint32_t a;
    asm("{ .reg .u64 tmp; cvta.to.shared.u64 tmp, %1; cvt.u32.u64 %0, tmp; }"
        : "=r"(a) : "l"(p));
    return a;
}
__device__ __forceinline__ void mbar_init(uint32_t mbar, uint32_t cnt) {
    asm volatile("mbarrier.init.shared.b64 [%0], %1;" :: "r"(mbar), "r"(cnt) : "memory");
}
__device__ __forceinline__ void mbar_expect_tx(uint32_t mbar, uint32_t bytes) {
    asm volatile("mbarrier.arrive.expect_tx.shared.b64 _, [%0], %1;"
                 :: "r"(mbar), "r"(bytes) : "memory");
}
__device__ __forceinline__ void mbar_arrive(uint32_t mbar) {
    asm volatile("mbarrier.arrive.shared.b64 _, [%0];" :: "r"(mbar) : "memory");
}
__device__ __forceinline__ void mbar_wait(uint32_t mbar, uint32_t parity) {
    uint32_t done;
    asm volatile(
        "{\n\t.reg .pred p;\n\t"
        "mbarrier.try_wait.parity.acquire.cta.shared::cta.b64 p, [%1], %2;\n\t"
        "selp.b32 %0, 1, 0, p;\n\t}"
        : "=r"(done) : "r"(mbar), "r"(parity) : "memory");
    if (!done) {
        asm volatile(
            "{\n\t.reg .pred P1;\n\t"
            "WL_%=:\n\t"
            "mbarrier.try_wait.parity.acquire.cta.shared::cta.b64 P1, [%0], %1, 0x989680;\n\t"
            "@P1 bra.uni WD_%=;\n\t"
            "bra.uni WL_%=;\n\t"
            "WD_%=:\n\t}"
            :: "r"(mbar), "r"(parity) : "memory");
    }
}
__device__ __forceinline__ void bulk_copy_g2s(uint32_t dst_smem, const void* src,
                                              uint32_t bytes, uint32_t mbar) {
    asm volatile(
        "cp.async.bulk.shared::cta.global.mbarrier::complete_tx::bytes "
        "[%0], [%1], %2, [%3];"
        :: "r"(dst_smem), "l"(src), "r"(bytes), "r"(mbar) : "memory");
}

__global__ __launch_bounds__(NTHREADS)
void token_segment_sum_kernel(const float* __restrict__ x,
                              const int*   __restrict__ seg,
                              float*       __restrict__ out)
{
    __shared__ alignas(16) float4 buf[NSTAGES][SROWS * H4];   // 36 KB
    __shared__ alignas(8) uint64_t mb_full[NSTAGES];
    __shared__ alignas(8) uint64_t mb_empty[NSTAGES];
    __shared__ int bndt[MAX_TILES_PER_CTA][TOK_PER_BLK + 1];  // all my tiles' bounds

    const int bid  = blockIdx.x;
    const int t    = threadIdx.x;       // 0..223
    const int wid  = t >> 5;            // 0..6 (warp 6 = producer)
    const int lane = t & 31;

    // number of tiles this block owns (strided assignment: bid + k*GRID)
    const int nt = (NUM_TILES - bid + GRID_BLOCKS - 1) / GRID_BLOCKS;

    if (t < NSTAGES) {
        mbar_init(smem_u32(&mb_full[t]), 1);         // completed by TMA tx bytes
        mbar_init(smem_u32(&mb_empty[t]), NCWARPS);  // one arrive per consumer warp
    }

    // ---- bounds via windowed smem search (buf reused as staging) ----------
    // Stage a +-WMARGIN window of seg around each tile's token range: ONE
    // coalesced global round trip instead of ~12 dependent probes per search.
    int* wbuf = reinterpret_cast<int*>(&buf[0][0]);   // nt*WLEN ints <= 10.9 KB

    for (int idx = t; idx < nt * WLEN; idx += NTHREADS) {
        const int k = idx / WLEN;
        const int i = idx % WLEN;
        const int tileIdx = bid + k * GRID_BLOCKS;
        const int b  = tileIdx / TILES_PER_BATCH;
        const int j0 = (tileIdx % TILES_PER_BATCH) * TOK_PER_BLK;
        const int w_lo = max(0, j0 - WMARGIN);
        const int w_hi = min(L_, j0 + TOK_PER_BLK + 1 + WMARGIN);
        if (i < w_hi - w_lo)
            wbuf[k * WLEN + i] = __ldg(&seg[b * L_ + w_lo + i]);
    }
    __syncthreads();

    for (int idx = t; idx < nt * (TOK_PER_BLK + 1); idx += NTHREADS) {
        const int k = idx / (TOK_PER_BLK + 1);
        const int i = idx % (TOK_PER_BLK + 1);
        const int tileIdx = bid + k * GRID_BLOCKS;
        const int b  = tileIdx / TILES_PER_BATCH;
        const int j0 = (tileIdx % TILES_PER_BATCH) * TOK_PER_BLK;
        const int* __restrict__ segb = seg + b * L_;
        const int w_lo = max(0, j0 - WMARGIN);
        const int w_hi = min(L_, j0 + TOK_PER_BLK + 1 + WMARGIN);
        const int target = j0 + i;

        // window brackets all bounds for targets j0 .. j0+TOK_PER_BLK?
        const bool valid =
            (w_lo == 0  || __ldg(&segb[w_lo - 1]) < j0) &&
            (w_hi == L_ || __ldg(&segb[w_hi]) >= j0 + TOK_PER_BLK);

        int lo, hi;
        if (valid) {                     // fast: ~10 smem steps
            lo = 0; hi = w_hi - w_lo;
            const int* wb = &wbuf[k * WLEN];
            #pragma unroll 1
            while (lo < hi) {
                int mid = (lo + hi) >> 1;
                if (wb[mid] < target) lo = mid + 1; else hi = mid;
            }
            lo += w_lo;
        } else {                         // fallback: global search (any input)
            lo = 0; hi = L_;
            #pragma unroll 1
            while (lo < hi) {
                int mid = (lo + hi) >> 1;
                if (__ldg(&segb[mid]) < target) lo = mid + 1; else hi = mid;
            }
        }
        bndt[k][i] = lo;
    }
    __syncthreads();   // bounds ready; buf free for the pipeline

    if (wid == NCWARPS) {
        // -------- PRODUCER WARP: stream chunks continuously across tiles ----
        if (lane == 0) {
            int cc = 0;   // global chunk counter (stage = cc%3, lap = cc/3)
            #pragma unroll 1
            for (int k = 0; k < nt; k++) {
                const int tileIdx = bid + k * GRID_BLOCKS;
                const int b = tileIdx / TILES_PER_BATCH;
                const float4* __restrict__ xb =
                    reinterpret_cast<const float4*>(x + (size_t)b * L_ * H_);
                const int s0 = bndt[k][0];
                const int s1 = bndt[k][TOK_PER_BLK];
                #pragma unroll 1
                for (int rbase = s0; rbase < s1; rbase += SROWS) {
                    const int s = cc % NSTAGES;
                    const int u = cc / NSTAGES;
                    if (u > 0)
                        mbar_wait(smem_u32(&mb_empty[s]), (uint32_t)((u - 1) & 1));
                    const uint32_t bytes =
                        (uint32_t)min(SROWS, s1 - rbase) * (H_ * 4);
                    const uint32_t fm = smem_u32(&mb_full[s]);
                    mbar_expect_tx(fm, bytes);
                    bulk_copy_g2s(smem_u32(&buf[s][0]),
                                  &xb[(size_t)rbase * H4], bytes, fm);
                    cc++;
                }
            }
        }
        return;
    }

    // -------- CONSUMER WARPS (192 lanes) --------------------------------
    int cc = 0;   // must mirror producer's chunk sequence exactly
    #pragma unroll 1
    for (int k = 0; k < nt; k++) {
        const int tileIdx = bid + k * GRID_BLOCKS;
        const int b  = tileIdx / TILES_PER_BATCH;
        const int j0 = (tileIdx % TILES_PER_BATCH) * TOK_PER_BLK;
        float4* __restrict__ ob =
            reinterpret_cast<float4*>(out + (size_t)b * L_ * H_);

        const int s0 = bndt[k][0];
        const int s1 = bndt[k][TOK_PER_BLK];

        int j = 0;
        // tokens empty at the very start (bnd[j+1] == s0) -> zero rows
        #pragma unroll 1
        while (j < TOK_PER_BLK && bndt[k][j + 1] == s0) {
            ob[(size_t)(j0 + j) * H4 + t] = make_float4(0.f, 0.f, 0.f, 0.f);
            j++;
        }

        int nb = (j < TOK_PER_BLK) ? bndt[k][j + 1] : -1;
        float4 acc = make_float4(0.f, 0.f, 0.f, 0.f);

        #pragma unroll 1
        for (int rbase = s0; rbase < s1; rbase += SROWS) {
            const int s = cc % NSTAGES;
            const uint32_t ph = (uint32_t)((cc / NSTAGES) & 1);
            const int n = min(SROWS, s1 - rbase);

            mbar_wait(smem_u32(&mb_full[s]), ph);

            #pragma unroll
            for (int i = 0; i < SROWS; i++) {
                if (i < n) {
                    float4 v = buf[s][i * H4 + t];
                    acc.x += v.x; acc.y += v.y;
                    acc.z += v.z; acc.w += v.w;
                    const int pos1 = rbase + i + 1;
                    if (pos1 == nb) {          // token(s) end here
                        do {
                            ob[(size_t)(j0 + j) * H4 + t] = acc;
                            acc = make_float4(0.f, 0.f, 0.f, 0.f);
                            j++;
                            nb = (j < TOK_PER_BLK) ? bndt[k][j + 1] : -1;
                        } while (nb == pos1);  // equal bounds = empty tokens
                    }
                }
            }

            // release the stage — ONE arrive per consumer warp
            __syncwarp();
            if (lane == 0) mbar_arrive(smem_u32(&mb_empty[s]));
            cc++;
        }
    }
}

extern "C" void kernel_launch(void* const* d_in, const int* in_sizes, int n_in,
                              void* d_out, int out_size)
{
    const float* x   = (const float*)d_in[0];   // sequence_output  [B, L, H] f32
    const int*   seg = (const int*)  d_in[1];   // wordpiece_to_token [B, L] i32
    float*       out = (float*)d_out;           // [B, L, H] f32

    dim3 grid(GRID_BLOCKS);                     // 888 persistent blocks
    dim3 block(NTHREADS);                       // 224 threads (6+1 warps)
    token_segment_sum_kernel<<<grid, block>>>(x, seg, out);
}

// round 17
// speedup vs baseline: 1.1064x; 1.0811x over previous
#include <cuda_runtime.h>
#include <stdint.h>

// Problem constants: B=16, L=4096, H=768 (fp32)
#define B_ 16
#define L_ 4096
#define H_ 768
#define H4 (H_ / 4)            // 192 float4 lanes per row
#define TOK_PER_BLK 16         // tokens per block tile
#define SROWS 4                // rows per pipeline stage (12 KB)
#define NSTAGES 3              // pipeline depth (36 KB smem)
#define NCWARPS 6              // consumer warps (192 lanes)
#define NTHREADS 224           // 6 consumer warps + 1 producer warp
#define BLOCKS_PER_BATCH (L_ / TOK_PER_BLK)  // 256

__device__ __forceinline__ uint32_t smem_u32(const void* p) {
    uint32_t a;
    asm("{ .reg .u64 tmp; cvta.to.shared.u64 tmp, %1; cvt.u32.u64 %0, tmp; }"
        : "=r"(a) : "l"(p));
    return a;
}
__device__ __forceinline__ void mbar_init(uint32_t mbar, uint32_t cnt) {
    asm volatile("mbarrier.init.shared.b64 [%0], %1;" :: "r"(mbar), "r"(cnt) : "memory");
}
__device__ __forceinline__ void mbar_expect_tx(uint32_t mbar, uint32_t bytes) {
    asm volatile("mbarrier.arrive.expect_tx.shared.b64 _, [%0], %1;"
                 :: "r"(mbar), "r"(bytes) : "memory");
}
__device__ __forceinline__ void mbar_arrive(uint32_t mbar) {
    asm volatile("mbarrier.arrive.shared.b64 _, [%0];" :: "r"(mbar) : "memory");
}
__device__ __forceinline__ void mbar_wait(uint32_t mbar, uint32_t parity) {
    uint32_t done;
    asm volatile(
        "{\n\t.reg .pred p;\n\t"
        "mbarrier.try_wait.parity.acquire.cta.shared::cta.b64 p, [%1], %2;\n\t"
        "selp.b32 %0, 1, 0, p;\n\t}"
        : "=r"(done) : "r"(mbar), "r"(parity) : "memory");
    if (!done) {
        asm volatile(
            "{\n\t.reg .pred P1;\n\t"
            "WL_%=:\n\t"
            "mbarrier.try_wait.parity.acquire.cta.shared::cta.b64 P1, [%0], %1, 0x989680;\n\t"
            "@P1 bra.uni WD_%=;\n\t"
            "bra.uni WL_%=;\n\t"
            "WD_%=:\n\t}"
            :: "r"(mbar), "r"(parity) : "memory");
    }
}
__device__ __forceinline__ void bulk_copy_g2s(uint32_t dst_smem, const void* src,
                                              uint32_t bytes, uint32_t mbar) {
    asm volatile(
        "cp.async.bulk.shared::cta.global.mbarrier::complete_tx::bytes "
        "[%0], [%1], %2, [%3];"
        :: "r"(dst_smem), "l"(src), "r"(bytes), "r"(mbar) : "memory");
}
__device__ __forceinline__ int lower_bound_g(const int* __restrict__ a, int target) {
    int lo = 0, hi = L_;
    #pragma unroll 1
    while (lo < hi) {
        int mid = (lo + hi) >> 1;
        if (__ldg(&a[mid]) < target) lo = mid + 1; else hi = mid;
    }
    return lo;
}

__global__ __launch_bounds__(NTHREADS)
void token_segment_sum_kernel(const float* __restrict__ x,
                              const int*   __restrict__ seg,
                              float*       __restrict__ out)
{
    __shared__ alignas(16) float4 buf[NSTAGES][SROWS * H4];   // 36 KB
    __shared__ alignas(8) uint64_t mb_full[NSTAGES];
    __shared__ alignas(8) uint64_t mb_empty[NSTAGES];
    __shared__ int bnd[TOK_PER_BLK + 1];

    const int b    = blockIdx.x / BLOCKS_PER_BATCH;
    const int tile = blockIdx.x % BLOCKS_PER_BATCH;
    const int j0   = tile * TOK_PER_BLK;

    const int* __restrict__ segb = seg + b * L_;
    const int t    = threadIdx.x;       // 0..223
    const int wid  = t >> 5;            // 0..6 (warp 6 = producer)
    const int lane = t & 31;

    if (t < NSTAGES) {
        mbar_init(smem_u32(&mb_full[t]), 1);         // completed by TMA tx bytes
        mbar_init(smem_u32(&mb_empty[t]), NCWARPS);  // one arrive per consumer warp
    }
    __syncthreads();   // ONLY block-wide sync: mbarriers visible to all warps

    const float4* __restrict__ xb =
        reinterpret_cast<const float4*>(x + (size_t)b * L_ * H_);

    if (wid == NCWARPS) {
        // ---- PRODUCER WARP: finds s0/s1 itself, starts TMA immediately ----
        // lanes 0/1 search the two endpoints in parallel; no block sync needed
        const int target = j0 + ((lane == 1) ? TOK_PER_BLK : 0);
        const int myb = lower_bound_g(segb, target);
        const int S0 = __shfl_sync(0xffffffffu, myb, 0);
        const int S1 = __shfl_sync(0xffffffffu, myb, 1);

        if (lane == 0) {
            int cc = 0;   // chunk counter (stage = cc%3, lap = cc/3)
            #pragma unroll 1
            for (int rbase = S0; rbase < S1; rbase += SROWS) {
                const int s = cc % NSTAGES;
                const int u = cc / NSTAGES;
                if (u > 0)
                    mbar_wait(smem_u32(&mb_empty[s]), (uint32_t)((u - 1) & 1));
                const uint32_t bytes =
                    (uint32_t)min(SROWS, S1 - rbase) * (H_ * 4);
                const uint32_t fm = smem_u32(&mb_full[s]);
                mbar_expect_tx(fm, bytes);
                bulk_copy_g2s(smem_u32(&buf[s][0]),
                              &xb[(size_t)rbase * H4], bytes, fm);
                cc++;
            }
        }
        return;
    }

    // ---- CONSUMER WARPS (192 lanes): compute all 17 bounds concurrently ----
    if (t <= TOK_PER_BLK)
        bnd[t] = lower_bound_g(segb, j0 + t);
    // consumer-only barrier (producer warp never participates)
    asm volatile("bar.sync 1, %0;" :: "n"(NCWARPS * 32) : "memory");

    float4* __restrict__ ob =
        reinterpret_cast<float4*>(out + (size_t)b * L_ * H_);

    const int s0 = bnd[0];
    const int s1 = bnd[TOK_PER_BLK];

    int j = 0;
    // tokens empty at the very start (bnd[j+1] == s0) -> zero rows
    #pragma unroll 1
    while (j < TOK_PER_BLK && bnd[j + 1] == s0) {
        ob[(size_t)(j0 + j) * H4 + t] = make_float4(0.f, 0.f, 0.f, 0.f);
        j++;
    }

    // register-cached next boundary: common row path has NO shared-mem read
    int nb = (j < TOK_PER_BLK) ? bnd[j + 1] : -1;
    float4 acc = make_float4(0.f, 0.f, 0.f, 0.f);

    int cc = 0;
    #pragma unroll 1
    for (int rbase = s0; rbase < s1; rbase += SROWS) {
        const int s = cc % NSTAGES;
        const uint32_t ph = (uint32_t)((cc / NSTAGES) & 1);
        const int n = min(SROWS, s1 - rbase);

        mbar_wait(smem_u32(&mb_full[s]), ph);

        #pragma unroll
        for (int i = 0; i < SROWS; i++) {
            if (i < n) {
                float4 v = buf[s][i * H4 + t];
                acc.x += v.x; acc.y += v.y;
                acc.z += v.z; acc.w += v.w;
                const int pos1 = rbase + i + 1;
                if (pos1 == nb) {          // rare: token(s) end here
                    do {
                        ob[(size_t)(j0 + j) * H4 + t] = acc;
                        acc = make_float4(0.f, 0.f, 0.f, 0.f);
                        j++;
                        nb = (j < TOK_PER_BLK) ? bnd[j + 1] : -1;
                    } while (nb == pos1);  // equal bounds = empty tokens
                }
            }
        }

        // release the stage — ONE arrive per consumer warp
        __syncwarp();
        if (lane == 0) mbar_arrive(smem_u32(&mb_empty[s]));
        cc++;
    }
}

extern "C" void kernel_launch(void* const* d_in, const int* in_sizes, int n_in,
                              void* d_out, int out_size)
{
    const float* x   = (const float*)d_in[0];   // sequence_output  [B, L, H] f32
    const int*   seg = (const int*)  d_in[1];   // wordpiece_to_token [B, L] i32
    float*       out = (float*)d_out;           // [B, L, H] f32

    dim3 grid(B_ * BLOCKS_PER_BATCH);           // 4096 blocks (dynamic scheduling)
    dim3 block(NTHREADS);                       // 224 threads (6+1 warps)
    token_segment_sum_kernel<<<grid, block>>>(x, seg, out);
}